// round 7
// baseline (speedup 1.0000x reference)
#include <cuda_runtime.h>
#include <cstdint>

// PQLayer: x:(B,512) fp32, C:(64,256,8) fp32.
// codes == one_hot(argmax_k <x_bm, C_mk>) (exact for non-max, 1 ulp at max);
// x_hat row == C[m, kmax, :]. => 1M argmax-of-256 8-dim dots + 1.07 GB one-hot
// store. R4: BPT=4 to amortize codeword LDS 4x (L1 was the binding pipe at
// 79%), and zero-fill + scatter for codes to strip the per-element compares.

#define FEAT 512
#define Mn   64
#define Kn   256
#define Dn   8
#define TPB  128
#define BPT  4
#define ROWS (TPB * BPT)   // 512 b-rows per block

// ---- packed f32x2 helpers (Blackwell sm_103a; FFMA2 only via PTX) ----
__device__ __forceinline__ unsigned long long f2_mul(unsigned long long a,
                                                     unsigned long long b) {
    unsigned long long d;
    asm("mul.rn.f32x2 %0, %1, %2;" : "=l"(d) : "l"(a), "l"(b));
    return d;
}
__device__ __forceinline__ unsigned long long f2_fma(unsigned long long a,
                                                     unsigned long long b,
                                                     unsigned long long c) {
    unsigned long long d;
    asm("fma.rn.f32x2 %0, %1, %2, %3;" : "=l"(d) : "l"(a), "l"(b), "l"(c));
    return d;
}
__device__ __forceinline__ float2 f2_unpack(unsigned long long v) {
    float2 r;
    asm("mov.b64 {%0, %1}, %2;" : "=f"(r.x), "=f"(r.y) : "l"(v));
    return r;
}

__global__ void __launch_bounds__(TPB)
pq_kernel(const float* __restrict__ x,
          const float* __restrict__ C,
          float* __restrict__ xhat,    // may be null
          float* __restrict__ codes,   // may be null
          int nB)
{
    // C[m] tile: 256 k * 8 floats = 8 KB, as 512 x 16B
    __shared__ ulonglong2 sC[Kn * 2];

    const int m  = blockIdx.y;
    const int b0 = blockIdx.x * ROWS;

    // Stage C[m] into smem
    const ulonglong2* Cg = reinterpret_cast<const ulonglong2*>(C + (size_t)m * Kn * Dn);
    #pragma unroll
    for (int i = threadIdx.x; i < Kn * 2; i += TPB) sC[i] = Cg[i];
    __syncthreads();

    // Load x for BPT rows (tasks): row t lives at b0 + tid + t*TPB
    unsigned long long xp[BPT][4];
    bool vld[BPT];
    #pragma unroll
    for (int t = 0; t < BPT; ++t) {
        const int b = b0 + threadIdx.x + t * TPB;
        vld[t] = (b < nB);
        if (vld[t]) {
            const ulonglong2* xg =
                reinterpret_cast<const ulonglong2*>(x + (size_t)b * FEAT + m * Dn);
            ulonglong2 xl = xg[0];
            ulonglong2 xh = xg[1];
            xp[t][0] = xl.x; xp[t][1] = xl.y; xp[t][2] = xh.x; xp[t][3] = xh.y;
        } else {
            xp[t][0] = xp[t][1] = xp[t][2] = xp[t][3] = 0ull;
        }
    }

    float best[BPT];
    int   kb[BPT];
    #pragma unroll
    for (int t = 0; t < BPT; ++t) { best[t] = -3.4e38f; kb[t] = 0; }

    // Argmax loop: one broadcast codeword load feeds all BPT tasks.
    #pragma unroll 4
    for (int k = 0; k < Kn; ++k) {
        const ulonglong2 c01 = sC[2 * k];
        const ulonglong2 c23 = sC[2 * k + 1];
        #pragma unroll
        for (int t = 0; t < BPT; ++t) {
            unsigned long long acc = f2_mul(xp[t][0], c01.x);
            acc = f2_fma(xp[t][1], c01.y, acc);
            acc = f2_fma(xp[t][2], c23.x, acc);
            acc = f2_fma(xp[t][3], c23.y, acc);
            float2 ab = f2_unpack(acc);
            float dot = ab.x + ab.y;
            if (dot > best[t]) { best[t] = dot; kb[t] = k; }  // strict > => first idx on ties
        }
    }

    // x_hat rows straight from smem codebook
    if (xhat) {
        #pragma unroll
        for (int t = 0; t < BPT; ++t) {
            if (!vld[t]) continue;
            const int b = b0 + threadIdx.x + t * TPB;
            ulonglong2* o =
                reinterpret_cast<ulonglong2*>(xhat + (size_t)b * FEAT + m * Dn);
            o[0] = sC[2 * kb[t]];
            o[1] = sC[2 * kb[t] + 1];
        }
    }

    if (codes) {
        // Pass 1: zero-fill all ROWS x 256 floats for this (block, m) slab with
        // pure float4 stores (no compares).
        const float4 z = make_float4(0.f, 0.f, 0.f, 0.f);
        float4* base = reinterpret_cast<float4*>(codes) +
                       (((size_t)b0 * Mn + m) * Kn) / 4;
        const size_t row_stride4 = (size_t)Mn * Kn / 4;   // float4 between b-rows
        #pragma unroll 4
        for (int i = threadIdx.x; i < ROWS * (Kn / 4); i += TPB) {
            const int r  = i >> 6;        // row within block
            const int c4 = i & 63;
            if (b0 + r < nB)
                base[(size_t)r * row_stride4 + c4] = z;
        }
        // Order zero-fill (other threads) before this thread's scatter of 1.0f.
        __syncthreads();
        // Pass 2: scatter the single 1.0 per row.
        #pragma unroll
        for (int t = 0; t < BPT; ++t) {
            if (!vld[t]) continue;
            const int b = b0 + threadIdx.x + t * TPB;
            codes[(size_t)b * Mn * Kn + (size_t)m * Kn + kb[t]] = 1.0f;
        }
    }
}

extern "C" void kernel_launch(void* const* d_in, const int* in_sizes, int n_in,
                              void* d_out, int out_size)
{
    // Resolve inputs by size: x has B*512 elems, C has 64*256*8 = 131072 elems.
    const float* x = (const float*)d_in[0];
    const float* C = (const float*)d_in[1];
    int x_size = in_sizes[0];
    if (n_in >= 2 && in_sizes[0] == Mn * Kn * Dn && in_sizes[1] != Mn * Kn * Dn) {
        x = (const float*)d_in[1];
        C = (const float*)d_in[0];
        x_size = in_sizes[1];
    }
    const int nB = x_size / FEAT;

    const long long XH = (long long)nB * FEAT;        // x_hat elems
    const long long CD = (long long)nB * Mn * Kn;     // codes elems

    float* out   = (float*)d_out;
    float* xhat  = nullptr;
    float* codes = nullptr;
    if ((long long)out_size == XH + CD)      { xhat = out; codes = out + XH; }
    else if ((long long)out_size == XH)      { xhat = out; }
    else if ((long long)out_size == CD)      { codes = out; }
    else                                     { xhat = out; codes = out + XH; }

    dim3 grid((nB + ROWS - 1) / ROWS, Mn);
    pq_kernel<<<grid, TPB>>>(x, C, xhat, codes, nB);
}

// round 12
// speedup vs baseline: 1.4155x; 1.4155x over previous
#include <cuda_runtime.h>
#include <cstdint>

// PQLayer: x:(B,512) fp32, C:(64,256,8) fp32.
// codes == one_hot(argmax_k <x_bm, C_mk>); x_hat row == C[m,kmax,:].
// R7: BPT=2 (LDS amortization without the BPT=4 occupancy collapse) and a
// branch-based one-hot store (c4 is loop-invariant per thread).

#define FEAT 512
#define Mn   64
#define Kn   256
#define Dn   8
#define TPB  128
#define BPT  2
#define ROWS (TPB * BPT)   // 256 b-rows per block

// ---- packed f32x2 helpers (Blackwell sm_103a; FFMA2 only via PTX) ----
__device__ __forceinline__ unsigned long long f2_mul(unsigned long long a,
                                                     unsigned long long b) {
    unsigned long long d;
    asm("mul.rn.f32x2 %0, %1, %2;" : "=l"(d) : "l"(a), "l"(b));
    return d;
}
__device__ __forceinline__ unsigned long long f2_fma(unsigned long long a,
                                                     unsigned long long b,
                                                     unsigned long long c) {
    unsigned long long d;
    asm("fma.rn.f32x2 %0, %1, %2, %3;" : "=l"(d) : "l"(a), "l"(b), "l"(c));
    return d;
}
__device__ __forceinline__ float2 f2_unpack(unsigned long long v) {
    float2 r;
    asm("mov.b64 {%0, %1}, %2;" : "=f"(r.x), "=f"(r.y) : "l"(v));
    return r;
}

__global__ void __launch_bounds__(TPB)
pq_kernel(const float* __restrict__ x,
          const float* __restrict__ C,
          float* __restrict__ xhat,    // may be null
          float* __restrict__ codes,   // may be null
          int nB)
{
    __shared__ ulonglong2 sC[Kn * 2];   // 8 KB codebook tile for this m
    __shared__ int s_kb[ROWS];

    const int m  = blockIdx.y;
    const int b0 = blockIdx.x * ROWS;
    const bool full = (b0 + ROWS) <= nB;   // B % ROWS == 0 in practice

    // Stage C[m] into smem
    const ulonglong2* Cg = reinterpret_cast<const ulonglong2*>(C + (size_t)m * Kn * Dn);
    #pragma unroll
    for (int i = threadIdx.x; i < Kn * 2; i += TPB) sC[i] = Cg[i];
    __syncthreads();

    // Load x for BPT rows: row t at b0 + tid + t*TPB
    unsigned long long xp[BPT][4];
    #pragma unroll
    for (int t = 0; t < BPT; ++t) {
        const int b = b0 + threadIdx.x + t * TPB;
        if (full || b < nB) {
            const ulonglong2* xg =
                reinterpret_cast<const ulonglong2*>(x + (size_t)b * FEAT + m * Dn);
            ulonglong2 xl = xg[0];
            ulonglong2 xh = xg[1];
            xp[t][0] = xl.x; xp[t][1] = xl.y; xp[t][2] = xh.x; xp[t][3] = xh.y;
        } else {
            xp[t][0] = xp[t][1] = xp[t][2] = xp[t][3] = 0ull;
        }
    }

    float best[BPT];
    int   kb[BPT];
    #pragma unroll
    for (int t = 0; t < BPT; ++t) { best[t] = -3.4e38f; kb[t] = 0; }

    // Argmax: one broadcast codeword LDS pair feeds BPT dot products.
    #pragma unroll 4
    for (int k = 0; k < Kn; ++k) {
        const ulonglong2 c01 = sC[2 * k];
        const ulonglong2 c23 = sC[2 * k + 1];
        #pragma unroll
        for (int t = 0; t < BPT; ++t) {
            unsigned long long acc = f2_mul(xp[t][0], c01.x);
            acc = f2_fma(xp[t][1], c01.y, acc);
            acc = f2_fma(xp[t][2], c23.x, acc);
            acc = f2_fma(xp[t][3], c23.y, acc);
            float2 ab = f2_unpack(acc);
            float dot = ab.x + ab.y;
            if (dot > best[t]) { best[t] = dot; kb[t] = k; }  // strict > => first idx
        }
    }

    // x_hat rows straight from the smem codebook
    if (xhat) {
        #pragma unroll
        for (int t = 0; t < BPT; ++t) {
            const int b = b0 + threadIdx.x + t * TPB;
            if (full || b < nB) {
                ulonglong2* o =
                    reinterpret_cast<ulonglong2*>(xhat + (size_t)b * FEAT + m * Dn);
                o[0] = sC[2 * kb[t]];
                o[1] = sC[2 * kb[t] + 1];
            }
        }
    }

    if (codes) {
        #pragma unroll
        for (int t = 0; t < BPT; ++t) s_kb[threadIdx.x + t * TPB] = kb[t];
        __syncthreads();

        // Coalesced one-hot store. i = tid + j*TPB over ROWS*64 float4.
        // c4 = i & 63 == tid & 63 (loop-invariant); r = i >> 6 advances by 2/iter.
        const int c4 = threadIdx.x & 63;
        float4* base = reinterpret_cast<float4*>(codes) +
                       (((size_t)b0 * Mn + m) * Kn) / 4;
        const size_t row_stride4 = (size_t)Mn * Kn / 4;   // float4 between b-rows
        int r = threadIdx.x >> 6;                          // 0 or 1
        float4* p = base + (size_t)r * row_stride4 + c4;
        const size_t pstep = 2 * row_stride4;              // r += 2 per iteration
        #pragma unroll 4
        for (int j = 0; j < ROWS / 2; ++j, r += 2, p += pstep) {
            if (!full && (b0 + r >= nB)) break;
            const int kbr = s_kb[r];                       // broadcast LDS
            float4 v = make_float4(0.f, 0.f, 0.f, 0.f);
            if ((kbr >> 2) == c4) {                        // rare (1/64) hit path
                const int lane = kbr & 3;
                v.x = (lane == 0) ? 1.0f : 0.0f;
                v.y = (lane == 1) ? 1.0f : 0.0f;
                v.z = (lane == 2) ? 1.0f : 0.0f;
                v.w = (lane == 3) ? 1.0f : 0.0f;
            }
            *p = v;
        }
    }
}

extern "C" void kernel_launch(void* const* d_in, const int* in_sizes, int n_in,
                              void* d_out, int out_size)
{
    // Resolve inputs by size: x has B*512 elems, C has 64*256*8 = 131072 elems.
    const float* x = (const float*)d_in[0];
    const float* C = (const float*)d_in[1];
    int x_size = in_sizes[0];
    if (n_in >= 2 && in_sizes[0] == Mn * Kn * Dn && in_sizes[1] != Mn * Kn * Dn) {
        x = (const float*)d_in[1];
        C = (const float*)d_in[0];
        x_size = in_sizes[1];
    }
    const int nB = x_size / FEAT;

    const long long XH = (long long)nB * FEAT;        // x_hat elems
    const long long CD = (long long)nB * Mn * Kn;     // codes elems

    float* out   = (float*)d_out;
    float* xhat  = nullptr;
    float* codes = nullptr;
    if ((long long)out_size == XH + CD)      { xhat = out; codes = out + XH; }
    else if ((long long)out_size == XH)      { xhat = out; }
    else if ((long long)out_size == CD)      { codes = out; }
    else                                     { xhat = out; codes = out + XH; }

    dim3 grid((nB + ROWS - 1) / ROWS, Mn);
    pq_kernel<<<grid, TPB>>>(x, C, xhat, codes, nB);
}